// round 3
// baseline (speedup 1.0000x reference)
#include <cuda_runtime.h>
#include <cstdint>

// Problem shape (fixed by reference setup_inputs)
#define Bn 4
#define Cn 32
#define Hn 480
#define Wn 854
#define HWn (Hn * Wn)          // 409920
#define CHWn (Cn * HWn)
#define NPIX (Bn * HWn)        // 1639680

// ---------------------------------------------------------------------------
// NHWC accumulation scratch: scr[pix][c], 128B per pixel, 16B-aligned groups.
// Static __device__ arrays are zero-initialized at module load; the transpose
// kernel re-zeros every element it drains, so the "scratch is zero on entry"
// invariant holds for every call / graph replay.
// ---------------------------------------------------------------------------
__device__ float4 g_scr[NPIX * 8];

__device__ __forceinline__ void red4(float* p, float a, float b, float c, float d) {
    asm volatile("red.global.add.v4.f32 [%0], {%1, %2, %3, %4};"
                 :: "l"(p), "f"(a), "f"(b), "f"(c), "f"(d) : "memory");
}

// ---------------------------------------------------------------------------
// Scatter: one thread per source pixel. 4 bilinear corners x 8 channel-groups
// of red.v4 into NHWC scratch. Channel loads from im0 are warp-coalesced
// (consecutive pixels, fixed channel plane).
// ---------------------------------------------------------------------------
__global__ void __launch_bounds__(256) scatter_kernel(
    const float*  __restrict__ im0,
    const float2* __restrict__ flow)
{
    const int pix = blockIdx.x * blockDim.x + threadIdx.x;
    if (pix >= NPIX) return;

    const int b = pix / HWn;
    const int p = pix - b * HWn;
    const int y = p / Wn;
    const int x = p - y * Wn;

    const float2 f = flow[pix];
    const float tx = (float)x + f.x;
    const float ty = (float)y + f.y;
    const float x0f = floorf(tx);
    const float y0f = floorf(ty);
    const float fx = tx - x0f;
    const float fy = ty - y0f;
    const int x0 = (int)x0f;
    const int y0 = (int)y0f;
    const int x1 = x0 + 1;
    const int y1 = y0 + 1;

    const float gx = 1.f - fx;
    const float gy = 1.f - fy;
    const float w00 = gx * gy;
    const float w01 = fx * gy;
    const float w10 = gx * fy;
    const float w11 = fx * fy;

    const bool vx0 = (unsigned)x0 < (unsigned)Wn;
    const bool vx1 = (unsigned)x1 < (unsigned)Wn;
    const bool vy0 = (unsigned)y0 < (unsigned)Hn;
    const bool vy1 = (unsigned)y1 < (unsigned)Hn;
    const bool v00 = vy0 && vx0;
    const bool v01 = vy0 && vx1;
    const bool v10 = vy1 && vx0;
    const bool v11 = vy1 && vx1;

    float* scr = (float*)g_scr;
    const long long bb = (long long)b * HWn;
    const long long d00 = (bb + (long long)y0 * Wn + x0) * 32;  // used only if valid
    const long long d01 = d00 + 32;
    const long long d10 = d00 + (long long)Wn * 32;
    const long long d11 = d10 + 32;

    const float* __restrict__ src = im0 + (size_t)b * CHWn + p;

    #pragma unroll
    for (int g = 0; g < 8; g++) {
        const float a = src[(size_t)(4 * g + 0) * HWn];
        const float bv = src[(size_t)(4 * g + 1) * HWn];
        const float c = src[(size_t)(4 * g + 2) * HWn];
        const float d = src[(size_t)(4 * g + 3) * HWn];
        const int go = g * 4;
        if (v00) red4(scr + d00 + go, w00 * a, w00 * bv, w00 * c, w00 * d);
        if (v01) red4(scr + d01 + go, w01 * a, w01 * bv, w01 * c, w01 * d);
        if (v10) red4(scr + d10 + go, w10 * a, w10 * bv, w10 * c, w10 * d);
        if (v11) red4(scr + d11 + go, w11 * a, w11 * bv, w11 * c, w11 * d);
    }
}

// ---------------------------------------------------------------------------
// Drain: NHWC scratch -> NCHW output, and re-zero scratch behind itself.
// CTA = (32 x-pixels, 1 row, 1 batch). Load phase: each thread reads one
// float4 (4 channels) of one pixel -> 4KB contiguous per CTA. SMEM 32x33
// (conflict-free both phases). Store phase: coalesced per channel plane.
// ---------------------------------------------------------------------------
__global__ void __launch_bounds__(256) drain_kernel(float* __restrict__ out)
{
    __shared__ float sm[32][33];

    const int b = blockIdx.z;
    const int y = blockIdx.y;
    const int x0 = blockIdx.x * 32;
    const int t = threadIdx.x;

    const int j = t >> 3;      // pixel within tile, 0..31
    const int g = t & 7;       // channel group, 0..7
    const int x = x0 + j;

    float4 v = make_float4(0.f, 0.f, 0.f, 0.f);
    if (x < Wn) {
        const size_t pbase = ((size_t)b * HWn + (size_t)y * Wn + x) * 8;
        v = g_scr[pbase + g];
        g_scr[pbase + g] = make_float4(0.f, 0.f, 0.f, 0.f);
    }
    sm[g * 4 + 0][j] = v.x;
    sm[g * 4 + 1][j] = v.y;
    sm[g * 4 + 2][j] = v.z;
    sm[g * 4 + 3][j] = v.w;
    __syncthreads();

    const int xo = t & 31;
    const int c0 = t >> 5;     // 0..7
    if (x0 + xo < Wn) {
        float* ob = out + (size_t)b * CHWn + (size_t)y * Wn + x0 + xo;
        #pragma unroll
        for (int k = 0; k < 4; k++) {
            const int c = c0 + k * 8;
            ob[(size_t)c * HWn] = sm[c][xo];
        }
    }
}

// ---------------------------------------------------------------------------
// Harness entry: scatter into zeroed NHWC scratch, then drain (transpose to
// NCHW + re-zero scratch). Graph-capturable, allocation-free.
// ---------------------------------------------------------------------------
extern "C" void kernel_launch(void* const* d_in, const int* in_sizes, int n_in,
                              void* d_out, int out_size) {
    const float*  im0  = (const float*)d_in[0];
    const float2* flow = (const float2*)d_in[1];
    float* out = (float*)d_out;

    scatter_kernel<<<(NPIX + 255) / 256, 256>>>(im0, flow);

    dim3 grid((Wn + 31) / 32, Hn, Bn);
    drain_kernel<<<grid, 256>>>(out);
}

// round 4
// speedup vs baseline: 1.4725x; 1.4725x over previous
#include <cuda_runtime.h>
#include <cstdint>

// Problem shape (fixed by reference setup_inputs)
#define Bn 4
#define Cn 32
#define Hn 480
#define Wn 854
#define HWn (Hn * Wn)          // 409920
#define CHWn (Cn * HWn)

// ---------------------------------------------------------------------------
// NHWC accumulation slab for ONE batch: slab[pix][c], 52.5MB -> L2-resident.
// Reused for b=0..3 (scatter(b) then drain(b), stream-ordered). Statically
// zero at load; drain re-zeros everything it reads, so the "slab is zero on
// entry to scatter" invariant holds for every call / graph replay.
// ---------------------------------------------------------------------------
__device__ float4 g_slab[HWn * 8];

__device__ __forceinline__ void red4(float* p, float a, float b, float c, float d) {
    asm volatile("red.global.add.v4.f32 [%0], {%1, %2, %3, %4};"
                 :: "l"(p), "f"(a), "f"(b), "f"(c), "f"(d) : "memory");
}

// ---------------------------------------------------------------------------
// Scatter (one batch): one thread per source pixel, 4 corners x 8 channel-
// groups of red.v4 into the NHWC slab. im0 loads are warp-coalesced.
// ---------------------------------------------------------------------------
__global__ void __launch_bounds__(256) scatter_kernel(
    const float*  __restrict__ im0,
    const float2* __restrict__ flow,
    int b)
{
    const int p = blockIdx.x * blockDim.x + threadIdx.x;
    if (p >= HWn) return;

    const int y = p / Wn;
    const int x = p - y * Wn;

    const float2 f = flow[(size_t)b * HWn + p];
    const float tx = (float)x + f.x;
    const float ty = (float)y + f.y;
    const float x0f = floorf(tx);
    const float y0f = floorf(ty);
    const float fx = tx - x0f;
    const float fy = ty - y0f;
    const int x0 = (int)x0f;
    const int y0 = (int)y0f;

    const float gx = 1.f - fx;
    const float gy = 1.f - fy;
    const float w00 = gx * gy;
    const float w01 = fx * gy;
    const float w10 = gx * fy;
    const float w11 = fx * fy;

    const bool vx0 = (unsigned)x0 < (unsigned)Wn;
    const bool vx1 = (unsigned)(x0 + 1) < (unsigned)Wn;
    const bool vy0 = (unsigned)y0 < (unsigned)Hn;
    const bool vy1 = (unsigned)(y0 + 1) < (unsigned)Hn;
    const bool v00 = vy0 && vx0;
    const bool v01 = vy0 && vx1;
    const bool v10 = vy1 && vx0;
    const bool v11 = vy1 && vx1;

    float* slab = (float*)g_slab;
    const long long d00 = ((long long)y0 * Wn + x0) * 32;   // deref only if valid
    const long long d01 = d00 + 32;
    const long long d10 = d00 + (long long)Wn * 32;
    const long long d11 = d10 + 32;

    const float* __restrict__ src = im0 + (size_t)b * CHWn + p;

    #pragma unroll
    for (int g = 0; g < 8; g++) {
        const float a  = src[(size_t)(4 * g + 0) * HWn];
        const float bv = src[(size_t)(4 * g + 1) * HWn];
        const float c  = src[(size_t)(4 * g + 2) * HWn];
        const float d  = src[(size_t)(4 * g + 3) * HWn];
        const int go = g * 4;
        if (v00) red4(slab + d00 + go, w00 * a, w00 * bv, w00 * c, w00 * d);
        if (v01) red4(slab + d01 + go, w01 * a, w01 * bv, w01 * c, w01 * d);
        if (v10) red4(slab + d10 + go, w10 * a, w10 * bv, w10 * c, w10 * d);
        if (v11) red4(slab + d11 + go, w11 * a, w11 * bv, w11 * c, w11 * d);
    }
}

// ---------------------------------------------------------------------------
// Drain (one batch): NHWC slab -> NCHW output, re-zeroing the slab behind
// itself. CTA = 64 consecutive pixels of one row, all 32 channels.
// Phase 1: each thread loads 2 float4s (MLP=2, coalesced 8KB/CTA, L2-hit)
// and zero-stores them back. Phase 2: coalesced per-channel-plane stores.
// SMEM 32x65 (stride 65 ≡ 1 mod 32 -> conflict-free both phases).
// ---------------------------------------------------------------------------
__global__ void __launch_bounds__(256) drain_kernel(float* __restrict__ out, int b)
{
    __shared__ float sm[32][65];

    const int y  = blockIdx.y;
    const int x0 = blockIdx.x * 64;
    const int t  = threadIdx.x;

    const int j = t >> 3;      // pixel within half-tile, 0..31
    const int g = t & 7;       // channel group, 0..7

    const int xa = x0 + j;
    const int xb = xa + 32;

    float4 va = make_float4(0.f, 0.f, 0.f, 0.f);
    float4 vb = make_float4(0.f, 0.f, 0.f, 0.f);
    const size_t rowb = (size_t)y * Wn;
    if (xa < Wn) {
        const size_t ia = (rowb + xa) * 8 + g;
        va = g_slab[ia];
        g_slab[ia] = make_float4(0.f, 0.f, 0.f, 0.f);
    }
    if (xb < Wn) {
        const size_t ib = (rowb + xb) * 8 + g;
        vb = g_slab[ib];
        g_slab[ib] = make_float4(0.f, 0.f, 0.f, 0.f);
    }
    sm[g * 4 + 0][j]      = va.x;
    sm[g * 4 + 1][j]      = va.y;
    sm[g * 4 + 2][j]      = va.z;
    sm[g * 4 + 3][j]      = va.w;
    sm[g * 4 + 0][j + 32] = vb.x;
    sm[g * 4 + 1][j + 32] = vb.y;
    sm[g * 4 + 2][j + 32] = vb.z;
    sm[g * 4 + 3][j + 32] = vb.w;
    __syncthreads();

    const int xo = t & 31;
    const int c0 = t >> 5;     // 0..7
    float* ob = out + (size_t)b * CHWn + rowb + x0 + xo;
    const bool va2 = (x0 + xo) < Wn;
    const bool vb2 = (x0 + xo + 32) < Wn;
    #pragma unroll
    for (int k = 0; k < 4; k++) {
        const int c = c0 + k * 8;
        if (va2) ob[(size_t)c * HWn]      = sm[c][xo];
        if (vb2) ob[(size_t)c * HWn + 32] = sm[c][xo + 32];
    }
}

// ---------------------------------------------------------------------------
// Harness entry: per batch, scatter into the L2-resident slab then drain it
// (transpose + re-zero). 8 launches, graph-capturable, allocation-free.
// ---------------------------------------------------------------------------
extern "C" void kernel_launch(void* const* d_in, const int* in_sizes, int n_in,
                              void* d_out, int out_size) {
    const float*  im0  = (const float*)d_in[0];
    const float2* flow = (const float2*)d_in[1];
    float* out = (float*)d_out;

    const dim3 dgrid((Wn + 63) / 64, Hn, 1);
    for (int b = 0; b < Bn; b++) {
        scatter_kernel<<<(HWn + 255) / 256, 256>>>(im0, flow, b);
        drain_kernel<<<dgrid, 256>>>(out, b);
    }
}

// round 5
// speedup vs baseline: 1.7780x; 1.2075x over previous
#include <cuda_runtime.h>
#include <cstdint>

// Problem shape (fixed by reference setup_inputs)
#define Bn 4
#define Cn 32
#define Hn 480
#define Wn 854
#define HWn (Hn * Wn)          // 409920
#define CHWn (Cn * HWn)

// ---------------------------------------------------------------------------
// NHWC accumulation slab for ONE batch: slab[pix][c], 52.5MB -> L2-resident.
// Reused for b=0..3 (scatter(b) then drain(b), stream-ordered). Statically
// zero at load; drain re-zeros everything it reads, so the "slab is zero on
// entry to scatter" invariant holds for every call / graph replay.
// All OTHER traffic (im0, flow, out) uses streaming cache hints so it does
// not evict the slab from L2.
// ---------------------------------------------------------------------------
__device__ float4 g_slab[HWn * 8];

__device__ __forceinline__ void red4(float* p, float a, float b, float c, float d) {
    asm volatile("red.global.add.v4.f32 [%0], {%1, %2, %3, %4};"
                 :: "l"(p), "f"(a), "f"(b), "f"(c), "f"(d) : "memory");
}

// ---------------------------------------------------------------------------
// Scatter (one batch): one thread per source pixel, 4 corners x 8 channel-
// groups of red.v4 into the NHWC slab. im0/flow reads are streaming (evict-
// first) so the slab stays L2-resident.
// ---------------------------------------------------------------------------
__global__ void __launch_bounds__(256) scatter_kernel(
    const float*  __restrict__ im0,
    const float2* __restrict__ flow,
    int b)
{
    const int p = blockIdx.x * blockDim.x + threadIdx.x;
    if (p >= HWn) return;

    const int y = p / Wn;
    const int x = p - y * Wn;

    const float2 f = __ldcs(flow + (size_t)b * HWn + p);
    const float tx = (float)x + f.x;
    const float ty = (float)y + f.y;
    const float x0f = floorf(tx);
    const float y0f = floorf(ty);
    const float fx = tx - x0f;
    const float fy = ty - y0f;
    const int x0 = (int)x0f;
    const int y0 = (int)y0f;

    const float gx = 1.f - fx;
    const float gy = 1.f - fy;
    const float w00 = gx * gy;
    const float w01 = fx * gy;
    const float w10 = gx * fy;
    const float w11 = fx * fy;

    const bool vx0 = (unsigned)x0 < (unsigned)Wn;
    const bool vx1 = (unsigned)(x0 + 1) < (unsigned)Wn;
    const bool vy0 = (unsigned)y0 < (unsigned)Hn;
    const bool vy1 = (unsigned)(y0 + 1) < (unsigned)Hn;
    const bool v00 = vy0 && vx0;
    const bool v01 = vy0 && vx1;
    const bool v10 = vy1 && vx0;
    const bool v11 = vy1 && vx1;

    float* slab = (float*)g_slab;
    const long long d00 = ((long long)y0 * Wn + x0) * 32;   // deref only if valid
    const long long d01 = d00 + 32;
    const long long d10 = d00 + (long long)Wn * 32;
    const long long d11 = d10 + 32;

    const float* __restrict__ src = im0 + (size_t)b * CHWn + p;

    #pragma unroll
    for (int g = 0; g < 8; g++) {
        const float a  = __ldcs(src + (size_t)(4 * g + 0) * HWn);
        const float bv = __ldcs(src + (size_t)(4 * g + 1) * HWn);
        const float c  = __ldcs(src + (size_t)(4 * g + 2) * HWn);
        const float d  = __ldcs(src + (size_t)(4 * g + 3) * HWn);
        const int go = g * 4;
        if (v00) red4(slab + d00 + go, w00 * a, w00 * bv, w00 * c, w00 * d);
        if (v01) red4(slab + d01 + go, w01 * a, w01 * bv, w01 * c, w01 * d);
        if (v10) red4(slab + d10 + go, w10 * a, w10 * bv, w10 * c, w10 * d);
        if (v11) red4(slab + d11 + go, w11 * a, w11 * bv, w11 * c, w11 * d);
    }
}

// ---------------------------------------------------------------------------
// Drain (one batch): NHWC slab -> NCHW output, re-zeroing the slab behind
// itself. CTA = 256 consecutive pixels of one row x all 32 channels (32KB).
// Phase 1: each thread loads 8 independent float4s (MLP=8, fully coalesced,
// slab L2-hit) and zero-stores them back (zeros stay dirty in L2 for the
// next scatter). One barrier. Phase 2: 32 coalesced per-channel-plane
// streaming stores. SMEM [32][257] (stride 257 % 32 == 1, conflict-free in
// both phases).
// ---------------------------------------------------------------------------
#define DPX 256   // pixels per drain CTA

__global__ void __launch_bounds__(256) drain_kernel(float* __restrict__ out, int b)
{
    __shared__ float sm[Cn][DPX + 1];    // 32 x 257 floats = 32.9KB

    const int y  = blockIdx.y;
    const int x0 = blockIdx.x * DPX;
    const int t  = threadIdx.x;
    const size_t rowb = (size_t)y * Wn;

    const int g  = t & 7;        // channel group 0..7 (constant across i)
    const int j0 = t >> 3;       // base pixel-in-tile

    // Phase 1: 8 independent coalesced float4 loads + zero-stores.
    #pragma unroll
    for (int i = 0; i < 8; i++) {
        const int j = j0 + 32 * i;          // pixel in tile, 0..255
        const int x = x0 + j;
        float4 v = make_float4(0.f, 0.f, 0.f, 0.f);
        if (x < Wn) {
            const size_t ia = (rowb + x) * 8 + g;
            v = g_slab[ia];
            g_slab[ia] = make_float4(0.f, 0.f, 0.f, 0.f);
        }
        sm[g * 4 + 0][j] = v.x;
        sm[g * 4 + 1][j] = v.y;
        sm[g * 4 + 2][j] = v.z;
        sm[g * 4 + 3][j] = v.w;
    }
    __syncthreads();

    // Phase 2: thread t owns x-offset t; 32 coalesced plane stores.
    const int x = x0 + t;
    if (x < Wn) {
        float* ob = out + (size_t)b * CHWn + rowb + x;
        #pragma unroll
        for (int c = 0; c < Cn; c++) {
            __stcs(ob + (size_t)c * HWn, sm[c][t]);
        }
    }
}

// ---------------------------------------------------------------------------
// Harness entry: per batch, scatter into the L2-resident slab then drain it
// (transpose + re-zero). 8 launches, graph-capturable, allocation-free.
// ---------------------------------------------------------------------------
extern "C" void kernel_launch(void* const* d_in, const int* in_sizes, int n_in,
                              void* d_out, int out_size) {
    const float*  im0  = (const float*)d_in[0];
    const float2* flow = (const float2*)d_in[1];
    float* out = (float*)d_out;

    const dim3 dgrid((Wn + DPX - 1) / DPX, Hn, 1);
    for (int b = 0; b < Bn; b++) {
        scatter_kernel<<<(HWn + 255) / 256, 256>>>(im0, flow, b);
        drain_kernel<<<dgrid, 256>>>(out, b);
    }
}